// round 15
// baseline (speedup 1.0000x reference)
#include <cuda_runtime.h>
#include <cuda_bf16.h>
#include <cuda_fp16.h>
#include <math.h>
#include <stdint.h>

// Problem constants
#define B    64
#define T    512
#define VSZ  32000
#define EMB  512
#define HID  1024
#define ENC  1024
#define NROW (B*T)        // 32768
#define GATES4 (4*HID)    // 4096
#define FCK  (HID+ENC+EMB) // 2560

// Scratch
__device__ float g_e[B*EMB];
__device__ float g_hW[B*HID];
__device__ float g_scores[B*T];
__device__ float g_ctx[B*ENC];
__device__ float g_gates[B*GATES4];

// fp16 operands for the score GEMM
__device__ __half g_enc_h[NROW*ENC];   // 64MB
__device__ __half g_Wh[HID*ENC];       // 2MB

// ---------------------------------------------------------------------------
// helpers
// ---------------------------------------------------------------------------
__device__ __forceinline__ uint32_t smem_u32(const void* p) {
    uint32_t a;
    asm("{ .reg .u64 t; cvta.to.shared.u64 t, %1; cvt.u32.u64 %0, t; }" : "=r"(a) : "l"(p));
    return a;
}
__device__ __forceinline__ uint32_t swz128(uint32_t o) { return o ^ ((o >> 3) & 0x70u); }

__device__ __forceinline__ float tanh_fast(float x) {
    float e = __expf(2.f * x);
    return 1.f - __fdividef(2.f, e + 1.f);
}
__device__ __forceinline__ void cp16(uint32_t saddr, const void* gptr) {
    asm volatile("cp.async.cg.shared.global [%0], [%1], 16;"
                 :: "r"(saddr), "l"(__cvta_generic_to_global(gptr)) : "memory");
}
__device__ __forceinline__ void cp_commit() {
    asm volatile("cp.async.commit_group;" ::: "memory");
}
__device__ __forceinline__ void cp_wait1() {
    asm volatile("cp.async.wait_group 1;" ::: "memory");
}
__device__ __forceinline__ void cp_wait0() {
    asm volatile("cp.async.wait_group 0;" ::: "memory");
}
__device__ __forceinline__ void ldmx4(uint32_t* r, uint32_t addr) {
    asm volatile("ldmatrix.sync.aligned.m8n8.x4.shared.b16 {%0,%1,%2,%3}, [%4];"
                 : "=r"(r[0]), "=r"(r[1]), "=r"(r[2]), "=r"(r[3]) : "r"(addr));
}
// bf16 mma
__device__ __forceinline__ void mma16816(float* c, const uint32_t* a,
                                         uint32_t b0, uint32_t b1) {
    asm volatile(
        "mma.sync.aligned.m16n8k16.row.col.f32.bf16.bf16.f32 "
        "{%0,%1,%2,%3}, {%4,%5,%6,%7}, {%8,%9}, {%0,%1,%2,%3};"
        : "+f"(c[0]), "+f"(c[1]), "+f"(c[2]), "+f"(c[3])
        : "r"(a[0]), "r"(a[1]), "r"(a[2]), "r"(a[3]), "r"(b0), "r"(b1));
}
// fp16 mma
__device__ __forceinline__ void mma16816h(float* c, const uint32_t* a,
                                          uint32_t b0, uint32_t b1) {
    asm volatile(
        "mma.sync.aligned.m16n8k16.row.col.f32.f16.f16.f32 "
        "{%0,%1,%2,%3}, {%4,%5,%6,%7}, {%8,%9}, {%0,%1,%2,%3};"
        : "+f"(c[0]), "+f"(c[1]), "+f"(c[2]), "+f"(c[3])
        : "r"(a[0]), "r"(a[1]), "r"(a[2]), "r"(a[3]), "r"(b0), "r"(b1));
}
// bf16 hi/lo split
__device__ __forceinline__ void split4(float4 x, uint2& hi, uint2& lo) {
    unsigned short h0 = __bfloat16_as_ushort(__float2bfloat16(x.x));
    unsigned short h1 = __bfloat16_as_ushort(__float2bfloat16(x.y));
    unsigned short h2 = __bfloat16_as_ushort(__float2bfloat16(x.z));
    unsigned short h3 = __bfloat16_as_ushort(__float2bfloat16(x.w));
    unsigned short l0 = __bfloat16_as_ushort(__float2bfloat16(x.x - __bfloat162float(__ushort_as_bfloat16(h0))));
    unsigned short l1 = __bfloat16_as_ushort(__float2bfloat16(x.y - __bfloat162float(__ushort_as_bfloat16(h1))));
    unsigned short l2 = __bfloat16_as_ushort(__float2bfloat16(x.z - __bfloat162float(__ushort_as_bfloat16(h2))));
    unsigned short l3 = __bfloat16_as_ushort(__float2bfloat16(x.w - __bfloat162float(__ushort_as_bfloat16(h3))));
    hi.x = (uint32_t)h0 | ((uint32_t)h1 << 16);
    hi.y = (uint32_t)h2 | ((uint32_t)h3 << 16);
    lo.x = (uint32_t)l0 | ((uint32_t)l1 << 16);
    lo.y = (uint32_t)l2 | ((uint32_t)l3 << 16);
}
// fp16 single-plane pack
__device__ __forceinline__ uint2 pack4h(float4 x) {
    __half2 p0 = __floats2half2_rn(x.x, x.y);
    __half2 p1 = __floats2half2_rn(x.z, x.w);
    uint2 r;
    r.x = *(uint32_t*)&p0;
    r.y = *(uint32_t*)&p1;
    return r;
}

// ---------------------------------------------------------------------------
__global__ void init_kernel() {
    int i = blockIdx.x * blockDim.x + threadIdx.x;
    int stride = gridDim.x * blockDim.x;
    for (int idx = i; idx < B*T;   idx += stride) g_scores[idx] = 0.f;
    for (int idx = i; idx < B*ENC; idx += stride) g_ctx[idx] = 0.f;
}

__global__ void embed_kernel(const int* __restrict__ tok,
                             const float* __restrict__ emb) {
    int b = blockIdx.x;
    long r = (long)tok[b];
    for (int i = threadIdx.x; i < EMB; i += blockDim.x)
        g_e[b*EMB + i] = emb[r*EMB + i];
}

// enc -> fp16
__global__ void convert_enc_k(const float* __restrict__ enc) {
    int i = blockIdx.x * blockDim.x + threadIdx.x;
    int stride = gridDim.x * blockDim.x;
    const int n4 = (NROW*ENC) / 4;
    const float4* src = (const float4*)enc;
    uint2* dst = (uint2*)g_enc_h;
    for (int v = i; v < n4; v += stride)
        dst[v] = pack4h(src[v]);
}

// attn_W enc-part -> fp16
__global__ void convert_W_k(const float* __restrict__ attn_W) {
    int i = blockIdx.x * blockDim.x + threadIdx.x;
    int e0 = i * 4;
    int row = e0 >> 10, col = e0 & 1023;
    float4 x = *(const float4*)(attn_W + (size_t)row*(ENC+HID) + HID + col);
    ((uint2*)g_Wh)[i] = pack4h(x);
}

// ---------------------------------------------------------------------------
// Segmented-A GEMM: MODE 0 = bf16 3-pass (fp32-grade), MODE 1 = fp16 1-pass.
// ---------------------------------------------------------------------------
struct SegGemmParams {
    const float *A0, *A1, *A2;
    int lda0, lda1, lda2;
    const float *B0, *B1, *B2;
    int ldb0, ldb1, ldb2;
    int kend0, kend1;
    int nChunks;
    const float* bias;
    float* C; int ldc;
};

template<int NT, int MODE>
__global__ void __launch_bounds__(512, 1)
mma_gemm_kernel(SegGemmParams p) {
    extern __shared__ char smem[];
    const uint32_t sb = smem_u32(smem);
    constexpr int SF     = 16384 + NT * 256;
    constexpr int OFF_BT = 2 * SF;
    constexpr int BT_AL  = 8192;
    constexpr int BT_BH  = 16384;
    constexpr int BT_BL  = 16384 + NT * 128;
    constexpr int MF = (NT == 128) ? 2 : 1;
    constexpr int WM = 4 / MF;
    constexpr int WN = 16 / WM;
    constexpr int NF = NT / (WN * 8);
    constexpr int BV = NT / 32;
    const int tid = threadIdx.x, lane = tid & 31, wid = tid >> 5;
    const int m0  = (wid / WN) * (MF * 16);
    const int n0w = (wid % WN) * (NF * 8);
    const int nBase = blockIdx.x * NT;

    float acc[MF][NF][4];
    #pragma unroll
    for (int mf = 0; mf < MF; mf++)
        #pragma unroll
        for (int nf = 0; nf < NF; nf++)
            #pragma unroll
            for (int q = 0; q < 4; q++) acc[mf][nf][q] = 0.f;

    #define ISSUE(CH) do {                                                       \
        int k0_ = (CH) * 64;                                                     \
        const float* A_; int lda_; const float* Bp_; int ldb_; int kk_;          \
        if (k0_ < p.kend0)      { A_=p.A0; lda_=p.lda0; Bp_=p.B0; ldb_=p.ldb0; kk_=k0_; }         \
        else if (k0_ < p.kend1) { A_=p.A1; lda_=p.lda1; Bp_=p.B1; ldb_=p.ldb1; kk_=k0_-p.kend0; } \
        else                    { A_=p.A2; lda_=p.lda2; Bp_=p.B2; ldb_=p.ldb2; kk_=k0_-p.kend1; } \
        uint32_t st_ = sb + ((CH) & 1) * SF;                                      \
        _Pragma("unroll")                                                         \
        for (int t_ = 0; t_ < 2; ++t_) {                                          \
            int v_ = tid + t_ * 512; int r_ = v_ >> 4; int c_ = (v_ & 15) * 4;    \
            cp16(st_ + r_ * 256 + c_ * 4, A_ + (size_t)r_ * lda_ + kk_ + c_);     \
        }                                                                         \
        _Pragma("unroll")                                                         \
        for (int t_ = 0; t_ < BV; ++t_) {                                         \
            int v_ = tid + t_ * 512; int r_ = v_ >> 4; int c_ = (v_ & 15) * 4;    \
            cp16(st_ + 16384 + r_ * 256 + c_ * 4,                                 \
                 Bp_ + (size_t)(nBase + r_) * ldb_ + kk_ + c_);                   \
        }                                                                         \
        cp_commit();                                                              \
    } while (0)

    ISSUE(0);
    #pragma unroll 1
    for (int ch = 0; ch < p.nChunks; ++ch) {
        if (ch + 1 < p.nChunks) { ISSUE(ch + 1); cp_wait1(); }
        else                    { cp_wait0(); }
        __syncthreads();

        const char* fst = smem + (ch & 1) * SF;
        char* bt = smem + OFF_BT;
        #pragma unroll
        for (int t = 0; t < 2; ++t) {
            int v = tid + t * 512; int r = v >> 4; int c = (v & 15) * 4;
            float4 x = *(const float4*)(fst + r * 256 + c * 4);
            uint32_t off = swz128((uint32_t)(r * 128 + c * 2));
            if (MODE == 0) {
                uint2 hi, lo; split4(x, hi, lo);
                *(uint2*)(bt + off) = hi;
                *(uint2*)(bt + BT_AL + off) = lo;
            } else {
                *(uint2*)(bt + off) = pack4h(x);
            }
        }
        #pragma unroll
        for (int t = 0; t < BV; ++t) {
            int v = tid + t * 512; int r = v >> 4; int c = (v & 15) * 4;
            float4 x = *(const float4*)(fst + 16384 + r * 256 + c * 4);
            uint32_t off = swz128((uint32_t)(r * 128 + c * 2));
            if (MODE == 0) {
                uint2 hi, lo; split4(x, hi, lo);
                *(uint2*)(bt + BT_BH + off) = hi;
                *(uint2*)(bt + BT_BL + off) = lo;
            } else {
                *(uint2*)(bt + BT_BH + off) = pack4h(x);
            }
        }
        __syncthreads();

        const uint32_t aH = sb + OFF_BT;
        const uint32_t bH = aH + BT_BH;
        #pragma unroll
        for (int ks = 0; ks < 4; ++ks) {
            uint32_t ah[MF][4], al[MF][4];
            #pragma unroll
            for (int mf = 0; mf < MF; ++mf) {
                uint32_t rel = swz128((uint32_t)((m0 + mf*16 + (lane & 15)) * 128
                                      + ((lane >> 4) << 4) + ks * 32));
                ldmx4(ah[mf], aH + rel);
                if (MODE == 0) ldmx4(al[mf], aH + BT_AL + rel);
            }
            uint32_t bh[NF/2][4], bl[NF/2][4];
            #pragma unroll
            for (int bp = 0; bp < NF/2; ++bp) {
                uint32_t rel = swz128((uint32_t)((n0w + bp*16 + ((lane >> 4) << 3) + (lane & 7)) * 128
                                      + (((lane >> 3) & 1) << 4) + ks * 32));
                ldmx4(bh[bp], bH + rel);
                if (MODE == 0) ldmx4(bl[bp], bH + (BT_BL - BT_BH) + rel);
            }
            #pragma unroll
            for (int mf = 0; mf < MF; ++mf) {
                #pragma unroll
                for (int nf = 0; nf < NF; ++nf) {
                    uint32_t h0 = bh[nf >> 1][(nf & 1)*2], h1 = bh[nf >> 1][(nf & 1)*2 + 1];
                    if (MODE == 0) {
                        uint32_t l0 = bl[nf >> 1][(nf & 1)*2], l1 = bl[nf >> 1][(nf & 1)*2 + 1];
                        mma16816(acc[mf][nf], ah[mf], h0, h1);
                        mma16816(acc[mf][nf], ah[mf], l0, l1);
                        mma16816(acc[mf][nf], al[mf], h0, h1);
                    } else {
                        mma16816h(acc[mf][nf], ah[mf], h0, h1);
                    }
                }
            }
        }
    }
    #undef ISSUE

    const int groupID = lane >> 2, tig = lane & 3;
    #pragma unroll
    for (int mf = 0; mf < MF; ++mf) {
        #pragma unroll
        for (int nf = 0; nf < NF; ++nf) {
            int row = m0 + mf * 16 + groupID;
            int col = nBase + n0w + nf * 8 + tig * 2;
            float b0 = p.bias ? p.bias[col] : 0.f;
            float b1 = p.bias ? p.bias[col + 1] : 0.f;
            p.C[(size_t)row * p.ldc + col]           = acc[mf][nf][0] + b0;
            p.C[(size_t)row * p.ldc + col + 1]       = acc[mf][nf][1] + b1;
            p.C[(size_t)(row + 8) * p.ldc + col]     = acc[mf][nf][2] + b0;
            p.C[(size_t)(row + 8) * p.ldc + col + 1] = acc[mf][nf][3] + b1;
        }
    }
}

// ---------------------------------------------------------------------------
// Attention score kernel v8: round-11 config + fragment software pipeline.
// single-pass fp16, 512 threads, 16 warps (4x4), warp tile 64x32,
// 3-stage cp.async pipeline; fragments for s+1 loaded before s's MMAs.
// ---------------------------------------------------------------------------
#define MT 256
#define NT_S 128
#define ITERS5 16
#define OFF_BH5 32768
#define STG5    49152
#define SCORE_SMEM (3 * STG5)          // 147456

__global__ void __launch_bounds__(512, 1)
score_mma_kernel(const float* __restrict__ v_W) {
    extern __shared__ char smem[];
    const uint32_t sb = smem_u32(smem);
    const int tid = threadIdx.x;
    const int lane = tid & 31, wid = tid >> 5;
    const int m0 = (wid >> 2) * 64;
    const int n0 = (wid & 3) * 32;
    const int rowBase = blockIdx.x * MT;
    const int jBase   = blockIdx.y * NT_S;
    const int b = rowBase >> 9;

    float acc[4][4][4];
    #pragma unroll
    for (int mf = 0; mf < 4; mf++)
        #pragma unroll
        for (int nf = 0; nf < 4; nf++)
            #pragma unroll
            for (int q = 0; q < 4; q++) acc[mf][nf][q] = 0.f;

    #define ISSUE_LOAD5(IT) do {                                                \
        int k0_ = (IT) * 64;                                                    \
        uint32_t st_ = sb + ((IT) % 3) * STG5;                                  \
        _Pragma("unroll")                                                       \
        for (int t_ = 0; t_ < 4; ++t_) {                                        \
            int idx_ = tid + t_ * 512;                                          \
            int r_ = idx_ >> 3, c_ = idx_ & 7;                                  \
            cp16(st_ + swz128(r_ * 128 + c_ * 16),                              \
                 g_enc_h + ((size_t)(rowBase + r_) << 10) + k0_ + (c_ << 3));   \
        }                                                                       \
        _Pragma("unroll")                                                       \
        for (int t_ = 0; t_ < 2; ++t_) {                                        \
            int idx_ = tid + t_ * 512;                                          \
            int r_ = idx_ >> 3, c_ = idx_ & 7;                                  \
            cp16(st_ + OFF_BH5 + swz128(r_ * 128 + c_ * 16),                    \
                 g_Wh + ((size_t)(jBase + r_) << 10) + k0_ + (c_ << 3));        \
        }                                                                       \
        cp_commit();                                                            \
    } while (0)

    #define LOAD_FRAGS(S, AH, BH) do {                                          \
        _Pragma("unroll")                                                       \
        for (int mf_ = 0; mf_ < 4; ++mf_) {                                     \
            uint32_t rel_ = swz128((m0 + mf_*16 + (lane & 15)) * 128            \
                                   + ((lane >> 4) << 4) + (S) * 32);            \
            ldmx4((AH)[mf_], aH + rel_);                                        \
        }                                                                       \
        _Pragma("unroll")                                                       \
        for (int bp_ = 0; bp_ < 2; ++bp_) {                                     \
            uint32_t rel_ = swz128((n0 + bp_*16 + ((lane >> 4) << 3) + (lane & 7)) * 128 \
                                   + (((lane >> 3) & 1) << 4) + (S) * 32);      \
            ldmx4((BH)[bp_], bH + rel_);                                        \
        }                                                                       \
    } while (0)

    ISSUE_LOAD5(0);
    ISSUE_LOAD5(1);
    #pragma unroll 1
    for (int it = 0; it < ITERS5; ++it) {
        if (it == ITERS5 - 1) cp_wait0(); else cp_wait1();
        __syncthreads();
        if (it + 2 < ITERS5) ISSUE_LOAD5(it + 2);
        const uint32_t aH = sb + (it % 3) * STG5;
        const uint32_t bH = aH + OFF_BH5;

        uint32_t ahf[2][4][4], bhf[2][2][4];
        LOAD_FRAGS(0, ahf[0], bhf[0]);
        #pragma unroll
        for (int s = 0; s < 4; ++s) {
            int cur = s & 1;
            if (s < 3) LOAD_FRAGS(s + 1, ahf[cur ^ 1], bhf[cur ^ 1]);
            #pragma unroll
            for (int mf = 0; mf < 4; ++mf)
                #pragma unroll
                for (int nf = 0; nf < 4; ++nf)
                    mma16816h(acc[mf][nf], ahf[cur][mf],
                              bhf[cur][nf >> 1][(nf & 1) * 2],
                              bhf[cur][nf >> 1][(nf & 1) * 2 + 1]);
        }
    }

    __syncthreads();
    float* vs = (float*)smem;
    float* hw = vs + NT_S;
    if (tid < NT_S) {
        vs[tid] = v_W[jBase + tid];
        hw[tid] = g_hW[b * HID + tid + jBase];
    }
    __syncthreads();

    int groupID = lane >> 2, tig = lane & 3;
    #pragma unroll
    for (int mf = 0; mf < 4; ++mf) {
        int rowA = m0 + mf * 16 + groupID;
        float sA = 0.f, sB = 0.f;
        #pragma unroll
        for (int nf = 0; nf < 4; ++nf) {
            int col = n0 + nf * 8 + tig * 2;
            float v0 = vs[col], v1 = vs[col + 1];
            float w0 = hw[col], w1 = hw[col + 1];
            sA += v0 * tanh_fast(acc[mf][nf][0] + w0);
            sA += v1 * tanh_fast(acc[mf][nf][1] + w1);
            sB += v0 * tanh_fast(acc[mf][nf][2] + w0);
            sB += v1 * tanh_fast(acc[mf][nf][3] + w1);
        }
        sA += __shfl_xor_sync(0xffffffffu, sA, 1);
        sA += __shfl_xor_sync(0xffffffffu, sA, 2);
        sB += __shfl_xor_sync(0xffffffffu, sB, 1);
        sB += __shfl_xor_sync(0xffffffffu, sB, 2);
        if (tig == 0) {
            atomicAdd(&g_scores[rowBase + rowA], sA);
            atomicAdd(&g_scores[rowBase + rowA + 8], sB);
        }
    }
}

// ---------------------------------------------------------------------------
// softmax over T=512 per batch row
// ---------------------------------------------------------------------------
__global__ void softmax_kernel() {
    int b = blockIdx.x;
    int t = threadIdx.x;
    __shared__ float red[512];
    float s = g_scores[b*T + t];
    red[t] = s; __syncthreads();
    for (int off = 256; off > 0; off >>= 1) {
        if (t < off) red[t] = fmaxf(red[t], red[t+off]);
        __syncthreads();
    }
    float mx = red[0];
    __syncthreads();
    float e = expf(s - mx);
    red[t] = e; __syncthreads();
    for (int off = 256; off > 0; off >>= 1) {
        if (t < off) red[t] += red[t+off];
        __syncthreads();
    }
    g_scores[b*T + t] = e / red[0];
}

// ctx from fp16 enc (L2-resident), 8 t-splits
__global__ void ctx_kernel() {
    int b = blockIdx.x;
    int tchunk = T / gridDim.y;
    int t0 = blockIdx.y * tchunk;
    __shared__ float ws[512];
    for (int i = threadIdx.x; i < tchunk; i += blockDim.x)
        ws[i] = g_scores[b*T + t0 + i];
    __syncthreads();
    int col0 = threadIdx.x * 4;
    float acc[4] = {0.f, 0.f, 0.f, 0.f};
    const __half* eb = g_enc_h + (size_t)b*T*ENC + (size_t)t0*ENC + col0;
    for (int t = 0; t < tchunk; t++) {
        float wt = ws[t];
        uint2 v = *(const uint2*)(eb + (size_t)t*ENC);
        __half2 p0 = *(__half2*)&v.x;
        __half2 p1 = *(__half2*)&v.y;
        float2 f0 = __half22float2(p0);
        float2 f1 = __half22float2(p1);
        acc[0] = fmaf(wt, f0.x, acc[0]);
        acc[1] = fmaf(wt, f0.y, acc[1]);
        acc[2] = fmaf(wt, f1.x, acc[2]);
        acc[3] = fmaf(wt, f1.y, acc[3]);
    }
    #pragma unroll
    for (int q = 0; q < 4; q++)
        atomicAdd(&g_ctx[b*ENC + col0 + q], acc[q]);
}

__global__ void lstm_kernel(const float* __restrict__ b_ih,
                            const float* __restrict__ b_hh,
                            const float* __restrict__ c0,
                            float* __restrict__ h_new,
                            float* __restrict__ c_new) {
    int idx = blockIdx.x * blockDim.x + threadIdx.x;
    int b = idx >> 10, j = idx & 1023;
    const float* g4 = g_gates + b*GATES4;
    float ig = g4[j]        + b_ih[j]        + b_hh[j];
    float fg = g4[HID+j]    + b_ih[HID+j]    + b_hh[HID+j];
    float gg = g4[2*HID+j]  + b_ih[2*HID+j]  + b_hh[2*HID+j];
    float og = g4[3*HID+j]  + b_ih[3*HID+j]  + b_hh[3*HID+j];
    ig = 1.f/(1.f+expf(-ig));
    fg = 1.f/(1.f+expf(-fg));
    og = 1.f/(1.f+expf(-og));
    gg = tanhf(gg);
    float c = fg * c0[idx] + ig * gg;
    float h = og * tanhf(c);
    c_new[idx] = c;
    h_new[idx] = h;
}

// ---------------------------------------------------------------------------
extern "C" void kernel_launch(void* const* d_in, const int* in_sizes, int n_in,
                              void* d_out, int out_size) {
    const int*   tok     = (const int*)  d_in[0];
    const float* h0      = (const float*)d_in[1];
    const float* c0      = (const float*)d_in[2];
    const float* enc     = (const float*)d_in[3];
    const float* emb     = (const float*)d_in[4];
    const float* attn_W  = (const float*)d_in[5];
    const float* attn_b  = (const float*)d_in[6];
    const float* v_W     = (const float*)d_in[7];
    const float* W_ih    = (const float*)d_in[8];
    const float* W_hh    = (const float*)d_in[9];
    const float* b_ih    = (const float*)d_in[10];
    const float* b_hh    = (const float*)d_in[11];
    const float* fc_W    = (const float*)d_in[12];
    const float* fc_b    = (const float*)d_in[13];

    float* pred  = (float*)d_out;
    float* h_new = pred + (size_t)B*VSZ;
    float* c_new = h_new + (size_t)B*HID;

    float *d_e, *d_ctx, *d_gates, *d_hW;
    cudaGetSymbolAddress((void**)&d_e,     g_e);
    cudaGetSymbolAddress((void**)&d_hW,    g_hW);
    cudaGetSymbolAddress((void**)&d_ctx,   g_ctx);
    cudaGetSymbolAddress((void**)&d_gates, g_gates);

    // SMEM sizes (derived from kernel layout):
    // <64,0>:  2*(16384+16384) + (16384+8192) + 8192  = 98304
    // <64,1>:  2*(16384+16384) + 16384 + 8192         = 90112
    // <256,1>: 2*(16384+65536) + 16384 + 32768        = 212992
    constexpr int SMEM_G64  = 2 * (16384 + 64 * 256) + 16384 + 64 * 128 + 64 * 128;
    constexpr int SMEM_G64F = 2 * (16384 + 64 * 256) + 16384 + 64 * 128;
    constexpr int SMEM_G256 = 2 * (16384 + 256 * 256) + 16384 + 256 * 128;
    cudaFuncSetAttribute(score_mma_kernel,
                         cudaFuncAttributeMaxDynamicSharedMemorySize, SCORE_SMEM);
    cudaFuncSetAttribute((mma_gemm_kernel<256,1>),
                         cudaFuncAttributeMaxDynamicSharedMemorySize, SMEM_G256);
    cudaFuncSetAttribute((mma_gemm_kernel<64,0>),
                         cudaFuncAttributeMaxDynamicSharedMemorySize, SMEM_G64);
    cudaFuncSetAttribute((mma_gemm_kernel<64,1>),
                         cudaFuncAttributeMaxDynamicSharedMemorySize, SMEM_G64F);

    init_kernel<<<256, 256>>>();
    embed_kernel<<<B, 256>>>(tok, emb);
    convert_enc_k<<<4096, 256>>>(enc);
    convert_W_k<<<1024, 256>>>(attn_W);

    // hW = attn_b + h0 @ attn_W[:, :HID]^T  (bf16 3-pass, fp32-grade)
    {
        SegGemmParams p;
        p.A0 = p.A1 = p.A2 = h0;       p.lda0 = p.lda1 = p.lda2 = HID;
        p.B0 = p.B1 = p.B2 = attn_W;   p.ldb0 = p.ldb1 = p.ldb2 = ENC+HID;
        p.kend0 = HID; p.kend1 = HID;
        p.nChunks = HID/64;
        p.bias = attn_b; p.C = d_hW; p.ldc = HID;
        mma_gemm_kernel<64,0><<<HID/64, 512, SMEM_G64>>>(p);
    }

    score_mma_kernel<<<dim3(NROW/MT, HID/NT_S), 512, SCORE_SMEM>>>(v_W);
    softmax_kernel<<<B, T>>>();
    ctx_kernel<<<dim3(B, 8), 256>>>();

    // gates = [e|ctx|h0] @ [W_ih | W_hh]^T  (fp16 single-pass)
    {
        SegGemmParams p;
        p.A0 = d_e;   p.lda0 = EMB;
        p.A1 = d_ctx; p.lda1 = ENC;
        p.A2 = h0;    p.lda2 = HID;
        p.B0 = W_ih;        p.ldb0 = EMB+ENC;
        p.B1 = W_ih + EMB;  p.ldb1 = EMB+ENC;
        p.B2 = W_hh;        p.ldb2 = HID;
        p.kend0 = EMB; p.kend1 = EMB+ENC;
        p.nChunks = (EMB+ENC+HID)/64;
        p.bias = nullptr; p.C = d_gates; p.ldc = GATES4;
        mma_gemm_kernel<64,1><<<GATES4/64, 512, SMEM_G64F>>>(p);
    }

    lstm_kernel<<<(B*HID)/256, 256>>>(b_ih, b_hh, c0, h_new, c_new);

    // pred = fc_b + [h_new|ctx|e] @ fc_W^T  (fp16 single-pass, single wave)
    {
        SegGemmParams p;
        p.A0 = h_new; p.lda0 = HID;
        p.A1 = d_ctx; p.lda1 = ENC;
        p.A2 = d_e;   p.lda2 = EMB;
        p.B0 = fc_W;            p.ldb0 = FCK;
        p.B1 = fc_W + HID;      p.ldb1 = FCK;
        p.B2 = fc_W + HID+ENC;  p.ldb2 = FCK;
        p.kend0 = HID; p.kend1 = HID+ENC;
        p.nChunks = FCK/64;
        p.bias = fc_b; p.C = pred; p.ldc = VSZ;
        mma_gemm_kernel<256,1><<<VSZ/256, 512, SMEM_G256>>>(p);
    }
}

// round 16
// speedup vs baseline: 1.5063x; 1.5063x over previous
#include <cuda_runtime.h>
#include <cuda_bf16.h>
#include <cuda_fp16.h>
#include <math.h>
#include <stdint.h>

// Problem constants
#define B    64
#define T    512
#define VSZ  32000
#define EMB  512
#define HID  1024
#define ENC  1024
#define NROW (B*T)        // 32768
#define GATES4 (4*HID)    // 4096
#define FCK  (HID+ENC+EMB) // 2560

// Scratch
__device__ float g_e[B*EMB];
__device__ float g_hW[B*HID];
__device__ float g_scores[B*T];
__device__ float g_ctx[B*ENC];
__device__ float g_gates[B*GATES4];

// fp16 operands for the score GEMM
__device__ __half g_enc_h[NROW*ENC];   // 64MB
__device__ __half g_Wh[HID*ENC];       // 2MB

// ---------------------------------------------------------------------------
// helpers
// ---------------------------------------------------------------------------
__device__ __forceinline__ uint32_t smem_u32(const void* p) {
    uint32_t a;
    asm("{ .reg .u64 t; cvta.to.shared.u64 t, %1; cvt.u32.u64 %0, t; }" : "=r"(a) : "l"(p));
    return a;
}
__device__ __forceinline__ uint32_t swz128(uint32_t o) { return o ^ ((o >> 3) & 0x70u); }

__device__ __forceinline__ float tanh_fast(float x) {
    float e = __expf(2.f * x);
    return 1.f - __fdividef(2.f, e + 1.f);
}
__device__ __forceinline__ void cp16(uint32_t saddr, const void* gptr) {
    asm volatile("cp.async.cg.shared.global [%0], [%1], 16;"
                 :: "r"(saddr), "l"(__cvta_generic_to_global(gptr)) : "memory");
}
__device__ __forceinline__ void cp_commit() {
    asm volatile("cp.async.commit_group;" ::: "memory");
}
__device__ __forceinline__ void cp_wait1() {
    asm volatile("cp.async.wait_group 1;" ::: "memory");
}
__device__ __forceinline__ void cp_wait0() {
    asm volatile("cp.async.wait_group 0;" ::: "memory");
}
__device__ __forceinline__ void ldmx4(uint32_t* r, uint32_t addr) {
    asm volatile("ldmatrix.sync.aligned.m8n8.x4.shared.b16 {%0,%1,%2,%3}, [%4];"
                 : "=r"(r[0]), "=r"(r[1]), "=r"(r[2]), "=r"(r[3]) : "r"(addr));
}
// bf16 mma
__device__ __forceinline__ void mma16816(float* c, const uint32_t* a,
                                         uint32_t b0, uint32_t b1) {
    asm volatile(
        "mma.sync.aligned.m16n8k16.row.col.f32.bf16.bf16.f32 "
        "{%0,%1,%2,%3}, {%4,%5,%6,%7}, {%8,%9}, {%0,%1,%2,%3};"
        : "+f"(c[0]), "+f"(c[1]), "+f"(c[2]), "+f"(c[3])
        : "r"(a[0]), "r"(a[1]), "r"(a[2]), "r"(a[3]), "r"(b0), "r"(b1));
}
// fp16 mma
__device__ __forceinline__ void mma16816h(float* c, const uint32_t* a,
                                          uint32_t b0, uint32_t b1) {
    asm volatile(
        "mma.sync.aligned.m16n8k16.row.col.f32.f16.f16.f32 "
        "{%0,%1,%2,%3}, {%4,%5,%6,%7}, {%8,%9}, {%0,%1,%2,%3};"
        : "+f"(c[0]), "+f"(c[1]), "+f"(c[2]), "+f"(c[3])
        : "r"(a[0]), "r"(a[1]), "r"(a[2]), "r"(a[3]), "r"(b0), "r"(b1));
}
// bf16 hi/lo split
__device__ __forceinline__ void split4(float4 x, uint2& hi, uint2& lo) {
    unsigned short h0 = __bfloat16_as_ushort(__float2bfloat16(x.x));
    unsigned short h1 = __bfloat16_as_ushort(__float2bfloat16(x.y));
    unsigned short h2 = __bfloat16_as_ushort(__float2bfloat16(x.z));
    unsigned short h3 = __bfloat16_as_ushort(__float2bfloat16(x.w));
    unsigned short l0 = __bfloat16_as_ushort(__float2bfloat16(x.x - __bfloat162float(__ushort_as_bfloat16(h0))));
    unsigned short l1 = __bfloat16_as_ushort(__float2bfloat16(x.y - __bfloat162float(__ushort_as_bfloat16(h1))));
    unsigned short l2 = __bfloat16_as_ushort(__float2bfloat16(x.z - __bfloat162float(__ushort_as_bfloat16(h2))));
    unsigned short l3 = __bfloat16_as_ushort(__float2bfloat16(x.w - __bfloat162float(__ushort_as_bfloat16(h3))));
    hi.x = (uint32_t)h0 | ((uint32_t)h1 << 16);
    hi.y = (uint32_t)h2 | ((uint32_t)h3 << 16);
    lo.x = (uint32_t)l0 | ((uint32_t)l1 << 16);
    lo.y = (uint32_t)l2 | ((uint32_t)l3 << 16);
}
// fp16 single-plane pack
__device__ __forceinline__ uint2 pack4h(float4 x) {
    __half2 p0 = __floats2half2_rn(x.x, x.y);
    __half2 p1 = __floats2half2_rn(x.z, x.w);
    uint2 r;
    r.x = *(uint32_t*)&p0;
    r.y = *(uint32_t*)&p1;
    return r;
}

// ---------------------------------------------------------------------------
__global__ void init_kernel() {
    int i = blockIdx.x * blockDim.x + threadIdx.x;
    int stride = gridDim.x * blockDim.x;
    for (int idx = i; idx < B*T;   idx += stride) g_scores[idx] = 0.f;
    for (int idx = i; idx < B*ENC; idx += stride) g_ctx[idx] = 0.f;
}

__global__ void embed_kernel(const int* __restrict__ tok,
                             const float* __restrict__ emb) {
    int b = blockIdx.x;
    long r = (long)tok[b];
    for (int i = threadIdx.x; i < EMB; i += blockDim.x)
        g_e[b*EMB + i] = emb[r*EMB + i];
}

// enc -> fp16
__global__ void convert_enc_k(const float* __restrict__ enc) {
    int i = blockIdx.x * blockDim.x + threadIdx.x;
    int stride = gridDim.x * blockDim.x;
    const int n4 = (NROW*ENC) / 4;
    const float4* src = (const float4*)enc;
    uint2* dst = (uint2*)g_enc_h;
    for (int v = i; v < n4; v += stride)
        dst[v] = pack4h(src[v]);
}

// attn_W enc-part -> fp16
__global__ void convert_W_k(const float* __restrict__ attn_W) {
    int i = blockIdx.x * blockDim.x + threadIdx.x;
    int e0 = i * 4;
    int row = e0 >> 10, col = e0 & 1023;
    float4 x = *(const float4*)(attn_W + (size_t)row*(ENC+HID) + HID + col);
    ((uint2*)g_Wh)[i] = pack4h(x);
}

// ---------------------------------------------------------------------------
// Segmented-A GEMM: MODE 0 = bf16 3-pass (fp32-grade), MODE 1 = fp16 1-pass.
// ---------------------------------------------------------------------------
struct SegGemmParams {
    const float *A0, *A1, *A2;
    int lda0, lda1, lda2;
    const float *B0, *B1, *B2;
    int ldb0, ldb1, ldb2;
    int kend0, kend1;
    int nChunks;
    const float* bias;
    float* C; int ldc;
};

template<int NT, int MODE>
__global__ void __launch_bounds__(512, 1)
mma_gemm_kernel(SegGemmParams p) {
    extern __shared__ char smem[];
    const uint32_t sb = smem_u32(smem);
    constexpr int SF     = 16384 + NT * 256;
    constexpr int OFF_BT = 2 * SF;
    constexpr int BT_AL  = 8192;
    constexpr int BT_BH  = 16384;
    constexpr int BT_BL  = 16384 + NT * 128;
    constexpr int MF = (NT == 128) ? 2 : 1;
    constexpr int WM = 4 / MF;
    constexpr int WN = 16 / WM;
    constexpr int NF = NT / (WN * 8);
    constexpr int BV = NT / 32;
    const int tid = threadIdx.x, lane = tid & 31, wid = tid >> 5;
    const int m0  = (wid / WN) * (MF * 16);
    const int n0w = (wid % WN) * (NF * 8);
    const int nBase = blockIdx.x * NT;

    float acc[MF][NF][4];
    #pragma unroll
    for (int mf = 0; mf < MF; mf++)
        #pragma unroll
        for (int nf = 0; nf < NF; nf++)
            #pragma unroll
            for (int q = 0; q < 4; q++) acc[mf][nf][q] = 0.f;

    #define ISSUE(CH) do {                                                       \
        int k0_ = (CH) * 64;                                                     \
        const float* A_; int lda_; const float* Bp_; int ldb_; int kk_;          \
        if (k0_ < p.kend0)      { A_=p.A0; lda_=p.lda0; Bp_=p.B0; ldb_=p.ldb0; kk_=k0_; }         \
        else if (k0_ < p.kend1) { A_=p.A1; lda_=p.lda1; Bp_=p.B1; ldb_=p.ldb1; kk_=k0_-p.kend0; } \
        else                    { A_=p.A2; lda_=p.lda2; Bp_=p.B2; ldb_=p.ldb2; kk_=k0_-p.kend1; } \
        uint32_t st_ = sb + ((CH) & 1) * SF;                                      \
        _Pragma("unroll")                                                         \
        for (int t_ = 0; t_ < 2; ++t_) {                                          \
            int v_ = tid + t_ * 512; int r_ = v_ >> 4; int c_ = (v_ & 15) * 4;    \
            cp16(st_ + r_ * 256 + c_ * 4, A_ + (size_t)r_ * lda_ + kk_ + c_);     \
        }                                                                         \
        _Pragma("unroll")                                                         \
        for (int t_ = 0; t_ < BV; ++t_) {                                         \
            int v_ = tid + t_ * 512; int r_ = v_ >> 4; int c_ = (v_ & 15) * 4;    \
            cp16(st_ + 16384 + r_ * 256 + c_ * 4,                                 \
                 Bp_ + (size_t)(nBase + r_) * ldb_ + kk_ + c_);                   \
        }                                                                         \
        cp_commit();                                                              \
    } while (0)

    ISSUE(0);
    #pragma unroll 1
    for (int ch = 0; ch < p.nChunks; ++ch) {
        if (ch + 1 < p.nChunks) { ISSUE(ch + 1); cp_wait1(); }
        else                    { cp_wait0(); }
        __syncthreads();

        const char* fst = smem + (ch & 1) * SF;
        char* bt = smem + OFF_BT;
        #pragma unroll
        for (int t = 0; t < 2; ++t) {
            int v = tid + t * 512; int r = v >> 4; int c = (v & 15) * 4;
            float4 x = *(const float4*)(fst + r * 256 + c * 4);
            uint32_t off = swz128((uint32_t)(r * 128 + c * 2));
            if (MODE == 0) {
                uint2 hi, lo; split4(x, hi, lo);
                *(uint2*)(bt + off) = hi;
                *(uint2*)(bt + BT_AL + off) = lo;
            } else {
                *(uint2*)(bt + off) = pack4h(x);
            }
        }
        #pragma unroll
        for (int t = 0; t < BV; ++t) {
            int v = tid + t * 512; int r = v >> 4; int c = (v & 15) * 4;
            float4 x = *(const float4*)(fst + 16384 + r * 256 + c * 4);
            uint32_t off = swz128((uint32_t)(r * 128 + c * 2));
            if (MODE == 0) {
                uint2 hi, lo; split4(x, hi, lo);
                *(uint2*)(bt + BT_BH + off) = hi;
                *(uint2*)(bt + BT_BL + off) = lo;
            } else {
                *(uint2*)(bt + BT_BH + off) = pack4h(x);
            }
        }
        __syncthreads();

        const uint32_t aH = sb + OFF_BT;
        const uint32_t bH = aH + BT_BH;
        #pragma unroll
        for (int ks = 0; ks < 4; ++ks) {
            uint32_t ah[MF][4], al[MF][4];
            #pragma unroll
            for (int mf = 0; mf < MF; ++mf) {
                uint32_t rel = swz128((uint32_t)((m0 + mf*16 + (lane & 15)) * 128
                                      + ((lane >> 4) << 4) + ks * 32));
                ldmx4(ah[mf], aH + rel);
                if (MODE == 0) ldmx4(al[mf], aH + BT_AL + rel);
            }
            uint32_t bh[NF/2][4], bl[NF/2][4];
            #pragma unroll
            for (int bp = 0; bp < NF/2; ++bp) {
                uint32_t rel = swz128((uint32_t)((n0w + bp*16 + ((lane >> 4) << 3) + (lane & 7)) * 128
                                      + (((lane >> 3) & 1) << 4) + ks * 32));
                ldmx4(bh[bp], bH + rel);
                if (MODE == 0) ldmx4(bl[bp], bH + (BT_BL - BT_BH) + rel);
            }
            #pragma unroll
            for (int mf = 0; mf < MF; ++mf) {
                #pragma unroll
                for (int nf = 0; nf < NF; ++nf) {
                    uint32_t h0 = bh[nf >> 1][(nf & 1)*2], h1 = bh[nf >> 1][(nf & 1)*2 + 1];
                    if (MODE == 0) {
                        uint32_t l0 = bl[nf >> 1][(nf & 1)*2], l1 = bl[nf >> 1][(nf & 1)*2 + 1];
                        mma16816(acc[mf][nf], ah[mf], h0, h1);
                        mma16816(acc[mf][nf], ah[mf], l0, l1);
                        mma16816(acc[mf][nf], al[mf], h0, h1);
                    } else {
                        mma16816h(acc[mf][nf], ah[mf], h0, h1);
                    }
                }
            }
        }
    }
    #undef ISSUE

    const int groupID = lane >> 2, tig = lane & 3;
    #pragma unroll
    for (int mf = 0; mf < MF; ++mf) {
        #pragma unroll
        for (int nf = 0; nf < NF; ++nf) {
            int row = m0 + mf * 16 + groupID;
            int col = nBase + n0w + nf * 8 + tig * 2;
            float b0 = p.bias ? p.bias[col] : 0.f;
            float b1 = p.bias ? p.bias[col + 1] : 0.f;
            p.C[(size_t)row * p.ldc + col]           = acc[mf][nf][0] + b0;
            p.C[(size_t)row * p.ldc + col + 1]       = acc[mf][nf][1] + b1;
            p.C[(size_t)(row + 8) * p.ldc + col]     = acc[mf][nf][2] + b0;
            p.C[(size_t)(row + 8) * p.ldc + col + 1] = acc[mf][nf][3] + b1;
        }
    }
}

// ---------------------------------------------------------------------------
// Attention score kernel v6 (round-11/14 champion, byte-exact):
// single-pass fp16, 512 threads, 16 warps (4x4), warp tile 64x32,
// 3-stage cp.async pipeline with wait_group 1. CTA: 256 rows x 128 j.
// ---------------------------------------------------------------------------
#define MT 256
#define NT_S 128
#define ITERS5 16
#define OFF_BH5 32768
#define STG5    49152
#define SCORE_SMEM (3 * STG5)          // 147456

__global__ void __launch_bounds__(512, 1)
score_mma_kernel(const float* __restrict__ v_W) {
    extern __shared__ char smem[];
    const uint32_t sb = smem_u32(smem);
    const int tid = threadIdx.x;
    const int lane = tid & 31, wid = tid >> 5;
    const int m0 = (wid >> 2) * 64;
    const int n0 = (wid & 3) * 32;
    const int rowBase = blockIdx.x * MT;
    const int jBase   = blockIdx.y * NT_S;
    const int b = rowBase >> 9;

    float acc[4][4][4];
    #pragma unroll
    for (int mf = 0; mf < 4; mf++)
        #pragma unroll
        for (int nf = 0; nf < 4; nf++)
            #pragma unroll
            for (int q = 0; q < 4; q++) acc[mf][nf][q] = 0.f;

    #define ISSUE_LOAD5(IT) do {                                                \
        int k0_ = (IT) * 64;                                                    \
        uint32_t st_ = sb + ((IT) % 3) * STG5;                                  \
        _Pragma("unroll")                                                       \
        for (int t_ = 0; t_ < 4; ++t_) {                                        \
            int idx_ = tid + t_ * 512;                                          \
            int r_ = idx_ >> 3, c_ = idx_ & 7;                                  \
            cp16(st_ + swz128(r_ * 128 + c_ * 16),                              \
                 g_enc_h + ((size_t)(rowBase + r_) << 10) + k0_ + (c_ << 3));   \
        }                                                                       \
        _Pragma("unroll")                                                       \
        for (int t_ = 0; t_ < 2; ++t_) {                                        \
            int idx_ = tid + t_ * 512;                                          \
            int r_ = idx_ >> 3, c_ = idx_ & 7;                                  \
            cp16(st_ + OFF_BH5 + swz128(r_ * 128 + c_ * 16),                    \
                 g_Wh + ((size_t)(jBase + r_) << 10) + k0_ + (c_ << 3));        \
        }                                                                       \
        cp_commit();                                                            \
    } while (0)

    ISSUE_LOAD5(0);
    ISSUE_LOAD5(1);
    #pragma unroll 1
    for (int it = 0; it < ITERS5; ++it) {
        if (it == ITERS5 - 1) cp_wait0(); else cp_wait1();
        __syncthreads();
        if (it + 2 < ITERS5) ISSUE_LOAD5(it + 2);
        const uint32_t aH = sb + (it % 3) * STG5;
        const uint32_t bH = aH + OFF_BH5;
        #pragma unroll
        for (int s = 0; s < 4; ++s) {
            uint32_t ah[4][4], bh[2][4];
            #pragma unroll
            for (int mf = 0; mf < 4; ++mf) {
                uint32_t rel = swz128((m0 + mf*16 + (lane & 15)) * 128
                                      + ((lane >> 4) << 4) + s * 32);
                ldmx4(ah[mf], aH + rel);
            }
            #pragma unroll
            for (int bp = 0; bp < 2; ++bp) {
                uint32_t rel = swz128((n0 + bp*16 + ((lane >> 4) << 3) + (lane & 7)) * 128
                                      + (((lane >> 3) & 1) << 4) + s * 32);
                ldmx4(bh[bp], bH + rel);
            }
            #pragma unroll
            for (int mf = 0; mf < 4; ++mf)
                #pragma unroll
                for (int nf = 0; nf < 4; ++nf)
                    mma16816h(acc[mf][nf], ah[mf],
                              bh[nf >> 1][(nf & 1) * 2], bh[nf >> 1][(nf & 1) * 2 + 1]);
        }
    }

    __syncthreads();
    float* vs = (float*)smem;
    float* hw = vs + NT_S;
    if (tid < NT_S) {
        vs[tid] = v_W[jBase + tid];
        hw[tid] = g_hW[b * HID + tid + jBase];
    }
    __syncthreads();

    int groupID = lane >> 2, tig = lane & 3;
    #pragma unroll
    for (int mf = 0; mf < 4; ++mf) {
        int rowA = m0 + mf * 16 + groupID;
        float sA = 0.f, sB = 0.f;
        #pragma unroll
        for (int nf = 0; nf < 4; ++nf) {
            int col = n0 + nf * 8 + tig * 2;
            float v0 = vs[col], v1 = vs[col + 1];
            float w0 = hw[col], w1 = hw[col + 1];
            sA += v0 * tanh_fast(acc[mf][nf][0] + w0);
            sA += v1 * tanh_fast(acc[mf][nf][1] + w1);
            sB += v0 * tanh_fast(acc[mf][nf][2] + w0);
            sB += v1 * tanh_fast(acc[mf][nf][3] + w1);
        }
        sA += __shfl_xor_sync(0xffffffffu, sA, 1);
        sA += __shfl_xor_sync(0xffffffffu, sA, 2);
        sB += __shfl_xor_sync(0xffffffffu, sB, 1);
        sB += __shfl_xor_sync(0xffffffffu, sB, 2);
        if (tig == 0) {
            atomicAdd(&g_scores[rowBase + rowA], sA);
            atomicAdd(&g_scores[rowBase + rowA + 8], sB);
        }
    }
}

// ---------------------------------------------------------------------------
// softmax over T=512 per batch row
// ---------------------------------------------------------------------------
__global__ void softmax_kernel() {
    int b = blockIdx.x;
    int t = threadIdx.x;
    __shared__ float red[512];
    float s = g_scores[b*T + t];
    red[t] = s; __syncthreads();
    for (int off = 256; off > 0; off >>= 1) {
        if (t < off) red[t] = fmaxf(red[t], red[t+off]);
        __syncthreads();
    }
    float mx = red[0];
    __syncthreads();
    float e = expf(s - mx);
    red[t] = e; __syncthreads();
    for (int off = 256; off > 0; off >>= 1) {
        if (t < off) red[t] += red[t+off];
        __syncthreads();
    }
    g_scores[b*T + t] = e / red[0];
}

// ctx from fp16 enc (L2-resident), 8 t-splits
__global__ void ctx_kernel() {
    int b = blockIdx.x;
    int tchunk = T / gridDim.y;
    int t0 = blockIdx.y * tchunk;
    __shared__ float ws[512];
    for (int i = threadIdx.x; i < tchunk; i += blockDim.x)
        ws[i] = g_scores[b*T + t0 + i];
    __syncthreads();
    int col0 = threadIdx.x * 4;
    float acc[4] = {0.f, 0.f, 0.f, 0.f};
    const __half* eb = g_enc_h + (size_t)b*T*ENC + (size_t)t0*ENC + col0;
    for (int t = 0; t < tchunk; t++) {
        float wt = ws[t];
        uint2 v = *(const uint2*)(eb + (size_t)t*ENC);
        __half2 p0 = *(__half2*)&v.x;
        __half2 p1 = *(__half2*)&v.y;
        float2 f0 = __half22float2(p0);
        float2 f1 = __half22float2(p1);
        acc[0] = fmaf(wt, f0.x, acc[0]);
        acc[1] = fmaf(wt, f0.y, acc[1]);
        acc[2] = fmaf(wt, f1.x, acc[2]);
        acc[3] = fmaf(wt, f1.y, acc[3]);
    }
    #pragma unroll
    for (int q = 0; q < 4; q++)
        atomicAdd(&g_ctx[b*ENC + col0 + q], acc[q]);
}

__global__ void lstm_kernel(const float* __restrict__ b_ih,
                            const float* __restrict__ b_hh,
                            const float* __restrict__ c0,
                            float* __restrict__ h_new,
                            float* __restrict__ c_new) {
    int idx = blockIdx.x * blockDim.x + threadIdx.x;
    int b = idx >> 10, j = idx & 1023;
    const float* g4 = g_gates + b*GATES4;
    float ig = g4[j]        + b_ih[j]        + b_hh[j];
    float fg = g4[HID+j]    + b_ih[HID+j]    + b_hh[HID+j];
    float gg = g4[2*HID+j]  + b_ih[2*HID+j]  + b_hh[2*HID+j];
    float og = g4[3*HID+j]  + b_ih[3*HID+j]  + b_hh[3*HID+j];
    ig = 1.f/(1.f+expf(-ig));
    fg = 1.f/(1.f+expf(-fg));
    og = 1.f/(1.f+expf(-og));
    gg = tanhf(gg);
    float c = fg * c0[idx] + ig * gg;
    float h = og * tanhf(c);
    c_new[idx] = c;
    h_new[idx] = h;
}

// ---------------------------------------------------------------------------
extern "C" void kernel_launch(void* const* d_in, const int* in_sizes, int n_in,
                              void* d_out, int out_size) {
    const int*   tok     = (const int*)  d_in[0];
    const float* h0      = (const float*)d_in[1];
    const float* c0      = (const float*)d_in[2];
    const float* enc     = (const float*)d_in[3];
    const float* emb     = (const float*)d_in[4];
    const float* attn_W  = (const float*)d_in[5];
    const float* attn_b  = (const float*)d_in[6];
    const float* v_W     = (const float*)d_in[7];
    const float* W_ih    = (const float*)d_in[8];
    const float* W_hh    = (const float*)d_in[9];
    const float* b_ih    = (const float*)d_in[10];
    const float* b_hh    = (const float*)d_in[11];
    const float* fc_W    = (const float*)d_in[12];
    const float* fc_b    = (const float*)d_in[13];

    float* pred  = (float*)d_out;
    float* h_new = pred + (size_t)B*VSZ;
    float* c_new = h_new + (size_t)B*HID;

    float *d_e, *d_ctx, *d_gates, *d_hW;
    cudaGetSymbolAddress((void**)&d_e,     g_e);
    cudaGetSymbolAddress((void**)&d_hW,    g_hW);
    cudaGetSymbolAddress((void**)&d_ctx,   g_ctx);
    cudaGetSymbolAddress((void**)&d_gates, g_gates);

    // SMEM sizes (derived from kernel layout):
    // <64,0>:  2*(16384+16384) + (16384+8192) + 8192  = 98304
    // <64,1>:  2*(16384+16384) + 16384 + 8192         = 90112
    // <256,1>: 2*(16384+65536) + 16384 + 32768        = 212992
    constexpr int SMEM_G64  = 2 * (16384 + 64 * 256) + 16384 + 64 * 128 + 64 * 128;
    constexpr int SMEM_G64F = 2 * (16384 + 64 * 256) + 16384 + 64 * 128;
    constexpr int SMEM_G256 = 2 * (16384 + 256 * 256) + 16384 + 256 * 128;
    cudaFuncSetAttribute(score_mma_kernel,
                         cudaFuncAttributeMaxDynamicSharedMemorySize, SCORE_SMEM);
    cudaFuncSetAttribute((mma_gemm_kernel<256,1>),
                         cudaFuncAttributeMaxDynamicSharedMemorySize, SMEM_G256);
    cudaFuncSetAttribute((mma_gemm_kernel<64,0>),
                         cudaFuncAttributeMaxDynamicSharedMemorySize, SMEM_G64);
    cudaFuncSetAttribute((mma_gemm_kernel<64,1>),
                         cudaFuncAttributeMaxDynamicSharedMemorySize, SMEM_G64F);

    init_kernel<<<256, 256>>>();
    embed_kernel<<<B, 256>>>(tok, emb);
    convert_enc_k<<<4096, 256>>>(enc);
    convert_W_k<<<1024, 256>>>(attn_W);

    // hW = attn_b + h0 @ attn_W[:, :HID]^T  (bf16 3-pass, fp32-grade)
    {
        SegGemmParams p;
        p.A0 = p.A1 = p.A2 = h0;       p.lda0 = p.lda1 = p.lda2 = HID;
        p.B0 = p.B1 = p.B2 = attn_W;   p.ldb0 = p.ldb1 = p.ldb2 = ENC+HID;
        p.kend0 = HID; p.kend1 = HID;
        p.nChunks = HID/64;
        p.bias = attn_b; p.C = d_hW; p.ldc = HID;
        mma_gemm_kernel<64,0><<<HID/64, 512, SMEM_G64>>>(p);
    }

    score_mma_kernel<<<dim3(NROW/MT, HID/NT_S), 512, SCORE_SMEM>>>(v_W);
    softmax_kernel<<<B, T>>>();
    ctx_kernel<<<dim3(B, 8), 256>>>();

    // gates = [e|ctx|h0] @ [W_ih | W_hh]^T  (fp16 single-pass)
    {
        SegGemmParams p;
        p.A0 = d_e;   p.lda0 = EMB;
        p.A1 = d_ctx; p.lda1 = ENC;
        p.A2 = h0;    p.lda2 = HID;
        p.B0 = W_ih;        p.ldb0 = EMB+ENC;
        p.B1 = W_ih + EMB;  p.ldb1 = EMB+ENC;
        p.B2 = W_hh;        p.ldb2 = HID;
        p.kend0 = EMB; p.kend1 = EMB+ENC;
        p.nChunks = (EMB+ENC+HID)/64;
        p.bias = nullptr; p.C = d_gates; p.ldc = GATES4;
        mma_gemm_kernel<64,1><<<GATES4/64, 512, SMEM_G64F>>>(p);
    }

    lstm_kernel<<<(B*HID)/256, 256>>>(b_ih, b_hh, c0, h_new, c_new);

    // pred = fc_b + [h_new|ctx|e] @ fc_W^T  (fp16 single-pass, single wave)
    {
        SegGemmParams p;
        p.A0 = h_new; p.lda0 = HID;
        p.A1 = d_ctx; p.lda1 = ENC;
        p.A2 = d_e;   p.lda2 = EMB;
        p.B0 = fc_W;            p.ldb0 = FCK;
        p.B1 = fc_W + HID;      p.ldb1 = FCK;
        p.B2 = fc_W + HID+ENC;  p.ldb2 = FCK;
        p.kend0 = HID; p.kend1 = HID+ENC;
        p.nChunks = FCK/64;
        p.bias = fc_b; p.C = pred; p.ldc = VSZ;
        mma_gemm_kernel<256,1><<<VSZ/256, 512, SMEM_G256>>>(p);
    }
}